// round 11
// baseline (speedup 1.0000x reference)
#include <cuda_runtime.h>
#include <cuda_fp16.h>
#include <cstdint>

#define NPTS 16384
#define BATCH 16
#define INC 7
typedef unsigned long long u64;
typedef unsigned int u32;

// ---------------- scratch ----------------
// k-major, plane-separated, k-pair packed: u32 = half2(val[2kp], val[2kp+1])
__device__ u32                g_hhi[(size_t)BATCH * 64 * NPTS]; // (b, kp, i)
__device__ u32                g_hlo[(size_t)BATCH * 64 * NPTS];
__device__ u32                g_wphi[1024 * 64];                // (c, kp) of 64*W
__device__ u32                g_wplo[1024 * 64];
__device__ unsigned char      g_gid[BATCH * NPTS];
__device__ unsigned long long g_pmax[BATCH * 1024];  // (valbits<<32)|(~idx)
__device__ unsigned int       g_gmax[4 * 1024];
__device__ float              g_u1[17 * 512];

__device__ __forceinline__ void split_limbs(float v, unsigned short& hi, unsigned short& lo) {
    __half h = __float2half_rn(v);
    float r = v - __half2float(h);
    __half l = __float2half_rn(r);
    hi = __half_as_ushort(h);
    lo = __half_as_ushort(l);
}
__device__ __forceinline__ void mma16(float* d, const u32* a, const u32* b) {
    asm volatile("mma.sync.aligned.m16n8k16.row.col.f32.f16.f16.f32 "
                 "{%0,%1,%2,%3}, {%4,%5,%6,%7}, {%8,%9}, {%0,%1,%2,%3};"
                 : "+f"(d[0]), "+f"(d[1]), "+f"(d[2]), "+f"(d[3])
                 : "r"(a[0]), "r"(a[1]), "r"(a[2]), "r"(a[3]), "r"(b[0]), "r"(b[1]));
}
__device__ __forceinline__ u32 smem_u32(const void* p) {
    u32 a; asm("{ .reg .u64 t; cvta.to.shared.u64 t, %1; cvt.u32.u64 %0, t; }" : "=r"(a) : "l"(p)); return a;
}
#define CP_ASYNC16(dst, src) asm volatile("cp.async.cg.shared.global [%0], [%1], 16;" :: "r"(dst), "l"(src) : "memory")
#define CP_COMMIT()  asm volatile("cp.async.commit_group;" ::: "memory")
#define CP_WAIT0()   asm volatile("cp.async.wait_group 0;" ::: "memory")
#define CP_WAIT1()   asm volatile("cp.async.wait_group 1;" ::: "memory")

// ---------------- kernel A: fused 7->64->64->64->128 + plane-split k-major output (R9 proven) ----------------
#define KA_SMEM_FLOATS 24704

__device__ __forceinline__ void smcpy128(float* dst, const float* src, int n, int tid) {
    for (int i = tid; i < n; i += 128) dst[i] = src[i];
}
__device__ __forceinline__ void mlp64s(const float* __restrict__ sw, const float* __restrict__ sb,
                                       const float* __restrict__ ain, float* __restrict__ aout, int tid) {
#pragma unroll 1
    for (int c0 = 0; c0 < 64; c0 += 8) {
        float acc[8];
#pragma unroll
        for (int u = 0; u < 8; u++) acc[u] = sb[c0 + u];
#pragma unroll 4
        for (int k = 0; k < 64; k += 4) {
            float a0 = ain[(k + 0) * 128 + tid];
            float a1 = ain[(k + 1) * 128 + tid];
            float a2 = ain[(k + 2) * 128 + tid];
            float a3 = ain[(k + 3) * 128 + tid];
#pragma unroll
            for (int u = 0; u < 8; u++) {
                float4 w4 = *reinterpret_cast<const float4*>(&sw[(c0 + u) * 64 + k]);
                acc[u] = fmaf(w4.x, a0, acc[u]);
                acc[u] = fmaf(w4.y, a1, acc[u]);
                acc[u] = fmaf(w4.z, a2, acc[u]);
                acc[u] = fmaf(w4.w, a3, acc[u]);
            }
        }
#pragma unroll
        for (int u = 0; u < 8; u++) aout[(c0 + u) * 128 + tid] = fmaxf(acc[u], 0.0f);
    }
}

__global__ __launch_bounds__(128, 2)
void kA(const float* __restrict__ points,
        const float* __restrict__ wl0, const float* __restrict__ bl0,
        const float* __restrict__ wl1, const float* __restrict__ bl1,
        const float* __restrict__ wl2, const float* __restrict__ bl2,
        const float* __restrict__ wl3, const float* __restrict__ bl3) {
    extern __shared__ float sm[];
    float* wbuf = sm;
    float* hA = sm + 8320;
    float* hB = sm + 16512;
    const int tid = threadIdx.x;

    smcpy128(wbuf + 0,    wl0, 448,  tid);
    smcpy128(wbuf + 448,  bl0, 64,   tid);
    smcpy128(wbuf + 512,  wl1, 4096, tid);
    smcpy128(wbuf + 4608, bl1, 64,   tid);

    const int p = blockIdx.x * 128 + tid;
    const int b = p >> 14;
    const int i = p & (NPTS - 1);
    const float* pt = points + (size_t)b * INC * NPTS + i;
    float x[INC];
#pragma unroll
    for (int c = 0; c < INC; c++) x[c] = pt[(size_t)c * NPTS];

    int g = 0; float bv = x[3];
    if (x[4] > bv) { bv = x[4]; g = 1; }
    if (x[5] > bv) { bv = x[5]; g = 2; }
    if (x[6] > bv) { bv = x[6]; g = 3; }
    g_gid[p] = (unsigned char)g;

    __syncthreads();
#pragma unroll 1
    for (int c0 = 0; c0 < 64; c0 += 8) {
        float acc[8];
#pragma unroll
        for (int u = 0; u < 8; u++) {
            const float* wr = &wbuf[(c0 + u) * 7];
            float s = wbuf[448 + c0 + u];
#pragma unroll
            for (int k = 0; k < 7; k++) s = fmaf(wr[k], x[k], s);
            acc[u] = s;
        }
#pragma unroll
        for (int u = 0; u < 8; u++) hA[(c0 + u) * 128 + tid] = fmaxf(acc[u], 0.0f);
    }
    mlp64s(wbuf + 512, wbuf + 4608, hA, hB, tid);   // L1
    __syncthreads();

    smcpy128(wbuf + 0,    wl2, 4096, tid);
    smcpy128(wbuf + 4096, bl2, 64,   tid);
    __syncthreads();
    mlp64s(wbuf + 0, wbuf + 4096, hB, hA, tid);     // L2
    __syncthreads();

    smcpy128(wbuf + 0,    wl3, 8192, tid);
    smcpy128(wbuf + 8192, bl3, 128,  tid);
    __syncthreads();

    u32* ophi = g_hhi + (size_t)b * 64 * NPTS + i;
    u32* oplo = g_hlo + (size_t)b * 64 * NPTS + i;
#pragma unroll 1
    for (int c0 = 0; c0 < 128; c0 += 8) {
        float acc[8];
#pragma unroll
        for (int u = 0; u < 8; u++) acc[u] = wbuf[8192 + c0 + u];
#pragma unroll 4
        for (int k = 0; k < 64; k += 4) {
            float a0 = hA[(k + 0) * 128 + tid];
            float a1 = hA[(k + 1) * 128 + tid];
            float a2 = hA[(k + 2) * 128 + tid];
            float a3 = hA[(k + 3) * 128 + tid];
#pragma unroll
            for (int u = 0; u < 8; u++) {
                float4 w4 = *reinterpret_cast<const float4*>(&wbuf[(c0 + u) * 64 + k]);
                acc[u] = fmaf(w4.x, a0, acc[u]);
                acc[u] = fmaf(w4.y, a1, acc[u]);
                acc[u] = fmaf(w4.z, a2, acc[u]);
                acc[u] = fmaf(w4.w, a3, acc[u]);
            }
        }
#pragma unroll
        for (int j = 0; j < 4; j++) {
            unsigned short h0, l0, h1, l1;
            split_limbs(fmaxf(acc[2 * j], 0.0f), h0, l0);
            split_limbs(fmaxf(acc[2 * j + 1], 0.0f), h1, l1);
            const size_t kp = (size_t)(c0 / 2 + j) * NPTS;
            ophi[kp] = (u32)h0 | ((u32)h1 << 16);
            oplo[kp] = (u32)l0 | ((u32)l1 << 16);
        }
    }
}

// ---------------- kernel W: split 64*W into fp16 limb planes, k-pair packed ----------------
__global__ void kW(const float* __restrict__ wl4) {
    int t = blockIdx.x * blockDim.x + threadIdx.x;
    if (t >= 1024 * 64) return;
    int c = t >> 6, kp = t & 63;
    unsigned short h0, l0, h1, l1;
    split_limbs(wl4[c * 128 + 2 * kp] * 64.0f, h0, l0);
    split_limbs(wl4[c * 128 + 2 * kp + 1] * 64.0f, h1, l1);
    g_wphi[t] = (u32)h0 | ((u32)h1 << 16);
    g_wplo[t] = (u32)l0 | ((u32)l1 << 16);
}

// ---------------- kernel B: 512-thread persistent 3-pass split-fp16 mma (R9 fragments) ----------------
#define WS2 68                       // W plane stride (u32)
#define HS2 136                      // H plane stride (u32)
#define KB_W_U (2 * 128 * WS2)       // 17408 u32
#define KB_H_U (2 * 64 * HS2)        // 17408 u32 per tile buffer
#define KB_SMEM_BYTES ((KB_W_U + 2 * KB_H_U) * 4)   // 208896 B

__global__ __launch_bounds__(512, 1)
void kB(const float* __restrict__ bl4) {
    extern __shared__ float smf[];
    u32* swp = reinterpret_cast<u32*>(smf);          // hi plane [128][WS2], lo at +128*WS2
    u32* hbuf0 = swp + KB_W_U;
    u32* hbuf1 = hbuf0 + KB_H_U;
    __shared__ unsigned char gid_s[128];

    const int tid = threadIdx.x;
    const int bid = blockIdx.x;
    const int b  = bid >> 6;
    const int pg = (bid >> 3) & 7;
    const int cc = bid & 7;
    const int c0 = cc * 128;

    // W tile: both planes, [r][kp] with stride WS2 (2048 uint4 chunks)
#pragma unroll
    for (int j = 0; j < 4; j++) {
        int idx = j * 512 + tid;
        int r = idx >> 4, q = (idx & 15) * 4;
        uint4 vh = *reinterpret_cast<const uint4*>(g_wphi + (size_t)(c0 + r) * 64 + q);
        uint4 vl = *reinterpret_cast<const uint4*>(g_wplo + (size_t)(c0 + r) * 64 + q);
        *reinterpret_cast<uint4*>(&swp[r * WS2 + q]) = vh;
        *reinterpret_cast<uint4*>(&swp[128 * WS2 + r * WS2 + q]) = vl;
    }

    const u32 hadd[2] = { smem_u32(hbuf0), smem_u32(hbuf1) };
    // prefetch H tile 0 (hi rows 0..63, lo rows 64..127; 4096 uint4 chunks)
    {
        const int pbase = pg * 2048;
#pragma unroll
        for (int j = 0; j < 8; j++) {
            int idx = j * 512 + tid;
            int row = idx >> 5, q = (idx & 31) * 4;
            const u32* src = (row < 64)
                ? g_hhi + ((size_t)b * 64 + row) * NPTS + pbase + q
                : g_hlo + ((size_t)b * 64 + (row - 64)) * NPTS + pbase + q;
            CP_ASYNC16(hadd[0] + (u32)(row * HS2 + q) * 4, src);
        }
        CP_COMMIT();
    }

    const int lane = tid & 31, wrp = tid >> 5;
    const int mw = wrp >> 2;            // 0..3: 32-channel slab
    const int nw = wrp & 3;             // 0..3: 32-point slab
    const int gid4 = lane >> 2, tig = lane & 3;
    const int cw = mw * 32, pw = nw * 32;

#pragma unroll 1
    for (int t = 0; t < 16; t++) {
        const int pbase = (pg * 16 + t) * 128;
        u32* shp = (t & 1) ? hbuf1 : hbuf0;
        if (t + 1 < 16) {
            const int pn = (pg * 16 + t + 1) * 128;
            const u32 dsta = hadd[(t + 1) & 1];
#pragma unroll
            for (int j = 0; j < 8; j++) {
                int idx = j * 512 + tid;
                int row = idx >> 5, q = (idx & 31) * 4;
                const u32* src = (row < 64)
                    ? g_hhi + ((size_t)b * 64 + row) * NPTS + pn + q
                    : g_hlo + ((size_t)b * 64 + (row - 64)) * NPTS + pn + q;
                CP_ASYNC16(dsta + (u32)(row * HS2 + q) * 4, src);
            }
            CP_COMMIT();
            CP_WAIT1();
        } else {
            CP_WAIT0();
        }
        if (tid < 128) gid_s[tid] = g_gid[b * NPTS + pbase + tid];
        __syncthreads();

        float acc[2][4][4];
#pragma unroll
        for (int mt = 0; mt < 2; mt++)
#pragma unroll
            for (int nt = 0; nt < 4; nt++)
#pragma unroll
                for (int j = 0; j < 4; j++) acc[mt][nt][j] = 0.0f;

        const u32* swhi = swp;
        const u32* swlo = swp + 128 * WS2;
        const u32* shhi = shp;
        const u32* shlo = shp + 64 * HS2;

#pragma unroll 1
        for (int kk = 0; kk < 8; kk++) {
            const int kpb = kk * 8;
            u32 ahi[2][4], alo[2][4];
#pragma unroll
            for (int mt = 0; mt < 2; mt++) {
                const int r0 = cw + mt * 16 + gid4;
#pragma unroll
                for (int q = 0; q < 4; q++) {
                    const int rr = r0 + (q & 1) * 8;
                    const int kq = kpb + tig + (q >> 1) * 4;
                    ahi[mt][q] = swhi[rr * WS2 + kq];
                    alo[mt][q] = swlo[rr * WS2 + kq];
                }
            }
            u32 bhi[4][2], blo[4][2];
#pragma unroll
            for (int nt = 0; nt < 4; nt++) {
                const int pp = pw + nt * 8 + gid4;
#pragma unroll
                for (int q = 0; q < 2; q++) {
                    const int kr = kpb + tig + q * 4;
                    bhi[nt][q] = shhi[kr * HS2 + pp];
                    blo[nt][q] = shlo[kr * HS2 + pp];
                }
            }
#pragma unroll
            for (int mt = 0; mt < 2; mt++)
#pragma unroll
                for (int nt = 0; nt < 4; nt++) {
                    mma16(acc[mt][nt], ahi[mt], bhi[nt]);
                    mma16(acc[mt][nt], ahi[mt], blo[nt]);
                    mma16(acc[mt][nt], alo[mt], bhi[nt]);
                }
        }
        __syncthreads();   // all reads of shp done; reuse region for staging

        u64* skey = reinterpret_cast<u64*>(shp);             // 128*16 u64 = 16 KB
        float* sg = reinterpret_cast<float*>(skey + 2048);   // 128*16*4 f32 = 32 KB
        const int slot = nw * 4 + tig;
#pragma unroll
        for (int mt = 0; mt < 2; mt++)
#pragma unroll
            for (int hf = 0; hf < 2; hf++) {
                const int c = cw + mt * 16 + gid4 + hf * 8;
                const float bias_c = __ldg(&bl4[c0 + c]);
                u64 key = 0ull;
                float g0 = 0.f, g1 = 0.f, g2 = 0.f, g3 = 0.f;
#pragma unroll
                for (int nt = 0; nt < 4; nt++)
#pragma unroll
                    for (int jj = 0; jj < 2; jj++) {
                        float val = fmaxf(fmaf(acc[mt][nt][hf * 2 + jj], 0.015625f, bias_c), 0.0f);
                        const int pl = pw + nt * 8 + tig * 2 + jj;
                        u64 k = ((u64)__float_as_uint(val) << 32) |
                                (u64)(0xFFFFFFFFu - (u32)(pbase + pl));
                        if (k > key) key = k;
                        const int gi = gid_s[pl];
                        g0 = fmaxf(g0, gi == 0 ? val : 0.f);
                        g1 = fmaxf(g1, gi == 1 ? val : 0.f);
                        g2 = fmaxf(g2, gi == 2 ? val : 0.f);
                        g3 = fmaxf(g3, gi == 3 ? val : 0.f);
                    }
                skey[c * 16 + slot] = key;
                sg[(c * 16 + slot) * 4 + 0] = g0;
                sg[(c * 16 + slot) * 4 + 1] = g1;
                sg[(c * 16 + slot) * 4 + 2] = g2;
                sg[(c * 16 + slot) * 4 + 3] = g3;
            }
        __syncthreads();

        if (tid < 128) {
            const int c = tid;
            u64 m = skey[c * 16];
            float mg[4] = { sg[c * 64 + 0], sg[c * 64 + 1], sg[c * 64 + 2], sg[c * 64 + 3] };
#pragma unroll
            for (int q = 1; q < 16; q++) {
                u64 e = skey[c * 16 + q];
                if (e > m) m = e;
#pragma unroll
                for (int g = 0; g < 4; g++) mg[g] = fmaxf(mg[g], sg[(c * 16 + q) * 4 + g]);
            }
            atomicMax(&g_pmax[b * 1024 + c0 + c], m);
#pragma unroll
            for (int g = 0; g < 4; g++)
                atomicMax(&g_gmax[g * 1024 + c0 + c], __float_as_uint(mg[g]));
        }
        __syncthreads();   // staging reads done before buffer is prefetch-overwritten
    }
}

// ---------------- init + tail MLPs (unchanged) ----------------
__global__ void kInit() {
    int t = blockIdx.x * blockDim.x + threadIdx.x;
    if (t < BATCH * 1024) g_pmax[t] = 0ull;
    if (t < 4 * 1024) g_gmax[t] = 0u;
}

__global__ void kC1(const float* __restrict__ wg0, const float* __restrict__ bg0,
                    const float* __restrict__ wgr0, const float* __restrict__ bgr0,
                    float* __restrict__ out) {
    const int gtid = blockIdx.x * blockDim.x + threadIdx.x;
    if (gtid < BATCH * 1024) {
        unsigned long long pv = g_pmax[gtid];
        out[4096 + gtid] = (float)(0xFFFFFFFFu - (unsigned int)(pv & 0xFFFFFFFFull));
    }
    const int wid = gtid >> 5;
    const int lane = gtid & 31;
    const int row = wid >> 9;
    const int j = wid & 511;
    if (row > 16) return;
    float s = 0.0f;
    if (row < 16) {
        const float* wr = wg0 + (size_t)j * 1024;
        const unsigned long long* pbuf = g_pmax + row * 1024;
        for (int k = lane; k < 1024; k += 32)
            s = fmaf(wr[k], __uint_as_float((unsigned int)(pbuf[k] >> 32)), s);
    } else {
        const float* wr = wgr0 + (size_t)j * 4096;
        for (int k = lane; k < 4096; k += 32)
            s = fmaf(wr[k], __uint_as_float(g_gmax[k]), s);
    }
#pragma unroll
    for (int o = 16; o; o >>= 1) s += __shfl_xor_sync(0xFFFFFFFFu, s, o);
    if (lane == 0) {
        float bb = (row < 16) ? bg0[j] : bgr0[j];
        g_u1[row * 512 + j] = fmaxf(s + bb, 0.0f);
    }
}

__global__ void kC2(const float* __restrict__ wg1, const float* __restrict__ bg1,
                    const float* __restrict__ wgr1, const float* __restrict__ bgr1,
                    float* __restrict__ out) {
    const int gtid = blockIdx.x * blockDim.x + threadIdx.x;
    const int wid = gtid >> 5;
    const int lane = gtid & 31;
    const int row = wid >> 7;
    const int j = wid & 127;
    if (row > 16) return;
    const float* wr = ((row < 16) ? wg1 : wgr1) + (size_t)j * 512;
    const float* in = g_u1 + row * 512;
    float s = 0.0f;
    for (int k = lane; k < 512; k += 32) s = fmaf(wr[k], in[k], s);
#pragma unroll
    for (int o = 16; o; o >>= 1) s += __shfl_xor_sync(0xFFFFFFFFu, s, o);
    s = __shfl_sync(0xFFFFFFFFu, s, 0);
    float bb = (row < 16) ? bg1[j] : bgr1[j];
    float val = fmaxf(s + bb, 0.0f);
    if (row < 16) {
        if (lane == 0) out[row * 256 + 128 + j] = val;
    } else {
        if (lane < 16) out[lane * 256 + j] = val;
    }
}

// ---------------- launch ----------------
extern "C" void kernel_launch(void* const* d_in, const int* in_sizes, int n_in,
                              void* d_out, int out_size) {
    const float* points = (const float*)d_in[0];
    const float* wl0 = (const float*)d_in[1];  const float* bl0 = (const float*)d_in[2];
    const float* wl1 = (const float*)d_in[3];  const float* bl1 = (const float*)d_in[4];
    const float* wl2 = (const float*)d_in[5];  const float* bl2 = (const float*)d_in[6];
    const float* wl3 = (const float*)d_in[7];  const float* bl3 = (const float*)d_in[8];
    const float* wl4 = (const float*)d_in[9];  const float* bl4 = (const float*)d_in[10];
    const float* wg0 = (const float*)d_in[11]; const float* bg0 = (const float*)d_in[12];
    const float* wg1 = (const float*)d_in[13]; const float* bg1 = (const float*)d_in[14];
    const float* wgr0 = (const float*)d_in[15]; const float* bgr0 = (const float*)d_in[16];
    const float* wgr1 = (const float*)d_in[17]; const float* bgr1 = (const float*)d_in[18];
    float* out = (float*)d_out;

    cudaFuncSetAttribute(kA, cudaFuncAttributeMaxDynamicSharedMemorySize,
                         KA_SMEM_FLOATS * (int)sizeof(float));
    cudaFuncSetAttribute(kB, cudaFuncAttributeMaxDynamicSharedMemorySize, KB_SMEM_BYTES);

    kInit<<<64, 256>>>();
    kW<<<256, 256>>>(wl4);
    kA<<<(BATCH * NPTS) / 128, 128, KA_SMEM_FLOATS * sizeof(float)>>>(
        points, wl0, bl0, wl1, bl1, wl2, bl2, wl3, bl3);
    kB<<<1024, 512, KB_SMEM_BYTES>>>(bl4);
    kC1<<<1088, 256>>>(wg0, bg0, wgr0, bgr0, out);
    kC2<<<272, 256>>>(wg1, bg1, wgr1, bgr1, out);
}

// round 12
// speedup vs baseline: 1.2405x; 1.2405x over previous
#include <cuda_runtime.h>
#include <cuda_fp16.h>
#include <cstdint>

#define NPTS 16384
#define BATCH 16
#define INC 7
typedef unsigned long long u64;
typedef unsigned int u32;

// ---------------- scratch ----------------
// k-major, plane-separated, k-pair packed: u32 = half2(val[2kp], val[2kp+1])
__device__ u32                g_hhi[(size_t)BATCH * 64 * NPTS]; // (b, kp, i)
__device__ u32                g_hlo[(size_t)BATCH * 64 * NPTS];
__device__ u32                g_wphi[1024 * 64];                // (c, kp) of 64*W
__device__ u32                g_wplo[1024 * 64];
__device__ unsigned char      g_gid[BATCH * NPTS];
__device__ unsigned long long g_pmax[BATCH * 1024];  // (valbits<<32)|(~idx)
__device__ unsigned int       g_gmax[4 * 1024];
__device__ float              g_u1[17 * 512];

__device__ __forceinline__ void split_limbs(float v, unsigned short& hi, unsigned short& lo) {
    __half h = __float2half_rn(v);
    float r = v - __half2float(h);
    __half l = __float2half_rn(r);
    hi = __half_as_ushort(h);
    lo = __half_as_ushort(l);
}
__device__ __forceinline__ void mma16(float* d, const u32* a, const u32* b) {
    asm volatile("mma.sync.aligned.m16n8k16.row.col.f32.f16.f16.f32 "
                 "{%0,%1,%2,%3}, {%4,%5,%6,%7}, {%8,%9}, {%0,%1,%2,%3};"
                 : "+f"(d[0]), "+f"(d[1]), "+f"(d[2]), "+f"(d[3])
                 : "r"(a[0]), "r"(a[1]), "r"(a[2]), "r"(a[3]), "r"(b[0]), "r"(b[1]));
}
__device__ __forceinline__ u32 smem_u32(const void* p) {
    u32 a; asm("{ .reg .u64 t; cvta.to.shared.u64 t, %1; cvt.u32.u64 %0, t; }" : "=r"(a) : "l"(p)); return a;
}
#define CP_ASYNC16(dst, src) asm volatile("cp.async.cg.shared.global [%0], [%1], 16;" :: "r"(dst), "l"(src) : "memory")
#define CP_COMMIT()  asm volatile("cp.async.commit_group;" ::: "memory")
#define CP_WAIT0()   asm volatile("cp.async.wait_group 0;" ::: "memory")
#define CP_WAIT1()   asm volatile("cp.async.wait_group 1;" ::: "memory")

// ---------------- kernel A: fused 7->64->64->64->128 + plane-split k-major output (R9 proven) ----------------
#define KA_SMEM_FLOATS 24704

__device__ __forceinline__ void smcpy128(float* dst, const float* src, int n, int tid) {
    for (int i = tid; i < n; i += 128) dst[i] = src[i];
}
__device__ __forceinline__ void mlp64s(const float* __restrict__ sw, const float* __restrict__ sb,
                                       const float* __restrict__ ain, float* __restrict__ aout, int tid) {
#pragma unroll 1
    for (int c0 = 0; c0 < 64; c0 += 8) {
        float acc[8];
#pragma unroll
        for (int u = 0; u < 8; u++) acc[u] = sb[c0 + u];
#pragma unroll 4
        for (int k = 0; k < 64; k += 4) {
            float a0 = ain[(k + 0) * 128 + tid];
            float a1 = ain[(k + 1) * 128 + tid];
            float a2 = ain[(k + 2) * 128 + tid];
            float a3 = ain[(k + 3) * 128 + tid];
#pragma unroll
            for (int u = 0; u < 8; u++) {
                float4 w4 = *reinterpret_cast<const float4*>(&sw[(c0 + u) * 64 + k]);
                acc[u] = fmaf(w4.x, a0, acc[u]);
                acc[u] = fmaf(w4.y, a1, acc[u]);
                acc[u] = fmaf(w4.z, a2, acc[u]);
                acc[u] = fmaf(w4.w, a3, acc[u]);
            }
        }
#pragma unroll
        for (int u = 0; u < 8; u++) aout[(c0 + u) * 128 + tid] = fmaxf(acc[u], 0.0f);
    }
}

__global__ __launch_bounds__(128, 2)
void kA(const float* __restrict__ points,
        const float* __restrict__ wl0, const float* __restrict__ bl0,
        const float* __restrict__ wl1, const float* __restrict__ bl1,
        const float* __restrict__ wl2, const float* __restrict__ bl2,
        const float* __restrict__ wl3, const float* __restrict__ bl3) {
    extern __shared__ float sm[];
    float* wbuf = sm;
    float* hA = sm + 8320;
    float* hB = sm + 16512;
    const int tid = threadIdx.x;

    smcpy128(wbuf + 0,    wl0, 448,  tid);
    smcpy128(wbuf + 448,  bl0, 64,   tid);
    smcpy128(wbuf + 512,  wl1, 4096, tid);
    smcpy128(wbuf + 4608, bl1, 64,   tid);

    const int p = blockIdx.x * 128 + tid;
    const int b = p >> 14;
    const int i = p & (NPTS - 1);
    const float* pt = points + (size_t)b * INC * NPTS + i;
    float x[INC];
#pragma unroll
    for (int c = 0; c < INC; c++) x[c] = pt[(size_t)c * NPTS];

    int g = 0; float bv = x[3];
    if (x[4] > bv) { bv = x[4]; g = 1; }
    if (x[5] > bv) { bv = x[5]; g = 2; }
    if (x[6] > bv) { bv = x[6]; g = 3; }
    g_gid[p] = (unsigned char)g;

    __syncthreads();
#pragma unroll 1
    for (int c0 = 0; c0 < 64; c0 += 8) {
        float acc[8];
#pragma unroll
        for (int u = 0; u < 8; u++) {
            const float* wr = &wbuf[(c0 + u) * 7];
            float s = wbuf[448 + c0 + u];
#pragma unroll
            for (int k = 0; k < 7; k++) s = fmaf(wr[k], x[k], s);
            acc[u] = s;
        }
#pragma unroll
        for (int u = 0; u < 8; u++) hA[(c0 + u) * 128 + tid] = fmaxf(acc[u], 0.0f);
    }
    mlp64s(wbuf + 512, wbuf + 4608, hA, hB, tid);   // L1
    __syncthreads();

    smcpy128(wbuf + 0,    wl2, 4096, tid);
    smcpy128(wbuf + 4096, bl2, 64,   tid);
    __syncthreads();
    mlp64s(wbuf + 0, wbuf + 4096, hB, hA, tid);     // L2
    __syncthreads();

    smcpy128(wbuf + 0,    wl3, 8192, tid);
    smcpy128(wbuf + 8192, bl3, 128,  tid);
    __syncthreads();

    u32* ophi = g_hhi + (size_t)b * 64 * NPTS + i;
    u32* oplo = g_hlo + (size_t)b * 64 * NPTS + i;
#pragma unroll 1
    for (int c0 = 0; c0 < 128; c0 += 8) {
        float acc[8];
#pragma unroll
        for (int u = 0; u < 8; u++) acc[u] = wbuf[8192 + c0 + u];
#pragma unroll 4
        for (int k = 0; k < 64; k += 4) {
            float a0 = hA[(k + 0) * 128 + tid];
            float a1 = hA[(k + 1) * 128 + tid];
            float a2 = hA[(k + 2) * 128 + tid];
            float a3 = hA[(k + 3) * 128 + tid];
#pragma unroll
            for (int u = 0; u < 8; u++) {
                float4 w4 = *reinterpret_cast<const float4*>(&wbuf[(c0 + u) * 64 + k]);
                acc[u] = fmaf(w4.x, a0, acc[u]);
                acc[u] = fmaf(w4.y, a1, acc[u]);
                acc[u] = fmaf(w4.z, a2, acc[u]);
                acc[u] = fmaf(w4.w, a3, acc[u]);
            }
        }
#pragma unroll
        for (int j = 0; j < 4; j++) {
            unsigned short h0, l0, h1, l1;
            split_limbs(fmaxf(acc[2 * j], 0.0f), h0, l0);
            split_limbs(fmaxf(acc[2 * j + 1], 0.0f), h1, l1);
            const size_t kp = (size_t)(c0 / 2 + j) * NPTS;
            ophi[kp] = (u32)h0 | ((u32)h1 << 16);
            oplo[kp] = (u32)l0 | ((u32)l1 << 16);
        }
    }
}

// ---------------- kernel W: split 64*W into fp16 limb planes, k-pair packed ----------------
__global__ void kW(const float* __restrict__ wl4) {
    int t = blockIdx.x * blockDim.x + threadIdx.x;
    if (t >= 1024 * 64) return;
    int c = t >> 6, kp = t & 63;
    unsigned short h0, l0, h1, l1;
    split_limbs(wl4[c * 128 + 2 * kp] * 64.0f, h0, l0);
    split_limbs(wl4[c * 128 + 2 * kp + 1] * 64.0f, h1, l1);
    g_wphi[t] = (u32)h0 | ((u32)h1 << 16);
    g_wplo[t] = (u32)l0 | ((u32)l1 << 16);
}

// ---------------- kernel B: R9 mainloop + register-running reductions (1 staging pass) ----------------
#define WS2 68                       // W plane stride (u32)
#define HS2 136                      // H plane stride (u32)
#define KB_W_U (2 * 128 * WS2)       // 17408 u32
#define KB_H_U (2 * 64 * HS2)        // 17408 u32 per tile buffer
#define KB_SMEM_BYTES ((KB_W_U + 2 * KB_H_U) * 4)   // 208896 B

__global__ __launch_bounds__(256, 1)
void kB(const float* __restrict__ bl4) {
    extern __shared__ float smf[];
    u32* swp = reinterpret_cast<u32*>(smf);          // hi plane [128][WS2], lo at +128*WS2
    u32* hbuf0 = swp + KB_W_U;
    u32* hbuf1 = hbuf0 + KB_H_U;
    __shared__ unsigned char gid_s[128];

    const int tid = threadIdx.x;
    const int bid = blockIdx.x;
    const int b  = bid >> 6;
    const int pg = (bid >> 3) & 7;
    const int cc = bid & 7;
    const int c0 = cc * 128;

    // W tile: both planes, [r][kp] with stride WS2
#pragma unroll
    for (int j = 0; j < 8; j++) {
        int idx = j * 256 + tid;                     // 2048 uint4 chunks
        int r = idx >> 4, q = (idx & 15) * 4;
        uint4 vh = *reinterpret_cast<const uint4*>(g_wphi + (size_t)(c0 + r) * 64 + q);
        uint4 vl = *reinterpret_cast<const uint4*>(g_wplo + (size_t)(c0 + r) * 64 + q);
        *reinterpret_cast<uint4*>(&swp[r * WS2 + q]) = vh;
        *reinterpret_cast<uint4*>(&swp[128 * WS2 + r * WS2 + q]) = vl;
    }

    const u32 hadd[2] = { smem_u32(hbuf0), smem_u32(hbuf1) };
    // prefetch H tile 0 (hi rows 0..63, lo rows 64..127)
    {
        const int pbase = pg * 2048;
#pragma unroll
        for (int j = 0; j < 16; j++) {
            int idx = j * 256 + tid;                 // 4096 uint4
            int row = idx >> 5, q = (idx & 31) * 4;
            const u32* src = (row < 64)
                ? g_hhi + ((size_t)b * 64 + row) * NPTS + pbase + q
                : g_hlo + ((size_t)b * 64 + (row - 64)) * NPTS + pbase + q;
            CP_ASYNC16(hadd[0] + (u32)(row * HS2 + q) * 4, src);
        }
        CP_COMMIT();
    }

    const int lane = tid & 31, wrp = tid >> 5;
    const int mw = wrp >> 1;
    const int nw = wrp & 1;
    const int gid4 = lane >> 2, tig = lane & 3;
    const int cw = mw * 32, pw = nw * 64;

    // per-thread running reductions over all tiles: 4 channels (mt,hf)
    float biasr[2][2];
    u64 pk[2][2];
    float gm[2][2][4];
#pragma unroll
    for (int mt = 0; mt < 2; mt++)
#pragma unroll
        for (int hf = 0; hf < 2; hf++) {
            biasr[mt][hf] = __ldg(&bl4[c0 + cw + mt * 16 + gid4 + hf * 8]);
            pk[mt][hf] = 0ull;
#pragma unroll
            for (int g = 0; g < 4; g++) gm[mt][hf][g] = 0.0f;
        }

#pragma unroll 1
    for (int t = 0; t < 16; t++) {
        const int pbase = (pg * 16 + t) * 128;
        u32* shp = (t & 1) ? hbuf1 : hbuf0;
        // prefetch next tile (its buffer's last readers were in iteration t-1, guarded by sync(b))
        if (t + 1 < 16) {
            const int pn = (pg * 16 + t + 1) * 128;
            const u32 dsta = hadd[(t + 1) & 1];
#pragma unroll
            for (int j = 0; j < 16; j++) {
                int idx = j * 256 + tid;
                int row = idx >> 5, q = (idx & 31) * 4;
                const u32* src = (row < 64)
                    ? g_hhi + ((size_t)b * 64 + row) * NPTS + pn + q
                    : g_hlo + ((size_t)b * 64 + (row - 64)) * NPTS + pn + q;
                CP_ASYNC16(dsta + (u32)(row * HS2 + q) * 4, src);
            }
            CP_COMMIT();
            CP_WAIT1();
        } else {
            CP_WAIT0();
        }
        if (tid < 128) gid_s[tid] = g_gid[b * NPTS + pbase + tid];
        __syncthreads();                 // sync(a): tile data + gid visible

        float acc[2][8][4];
#pragma unroll
        for (int mt = 0; mt < 2; mt++)
#pragma unroll
            for (int nt = 0; nt < 8; nt++)
#pragma unroll
                for (int j = 0; j < 4; j++) acc[mt][nt][j] = 0.0f;

        const u32* swhi = swp;
        const u32* swlo = swp + 128 * WS2;
        const u32* shhi = shp;
        const u32* shlo = shp + 64 * HS2;

#pragma unroll 1
        for (int kk = 0; kk < 8; kk++) {
            const int kpb = kk * 8;
            u32 ahi[2][4], alo[2][4];
#pragma unroll
            for (int mt = 0; mt < 2; mt++) {
                const int r0 = cw + mt * 16 + gid4;
#pragma unroll
                for (int q = 0; q < 4; q++) {
                    const int rr = r0 + (q & 1) * 8;
                    const int kq = kpb + tig + (q >> 1) * 4;
                    ahi[mt][q] = swhi[rr * WS2 + kq];
                    alo[mt][q] = swlo[rr * WS2 + kq];
                }
            }
            u32 bhi[8][2], blo[8][2];
#pragma unroll
            for (int nt = 0; nt < 8; nt++) {
                const int pp = pw + nt * 8 + gid4;
#pragma unroll
                for (int q = 0; q < 2; q++) {
                    const int kr = kpb + tig + q * 4;
                    bhi[nt][q] = shhi[kr * HS2 + pp];
                    blo[nt][q] = shlo[kr * HS2 + pp];
                }
            }
#pragma unroll
            for (int mt = 0; mt < 2; mt++)
#pragma unroll
                for (int nt = 0; nt < 8; nt++) {
                    mma16(acc[mt][nt], ahi[mt], bhi[nt]);
                    mma16(acc[mt][nt], ahi[mt], blo[nt]);
                    mma16(acc[mt][nt], alo[mt], bhi[nt]);
                }
        }

        // register-running epilogue: bias + relu + key/group-max updates (no smem, no sync)
#pragma unroll
        for (int mt = 0; mt < 2; mt++)
#pragma unroll
            for (int hf = 0; hf < 2; hf++) {
                const float bias_c = biasr[mt][hf];
                u64 key = pk[mt][hf];
                float g0 = gm[mt][hf][0], g1 = gm[mt][hf][1];
                float g2 = gm[mt][hf][2], g3 = gm[mt][hf][3];
#pragma unroll
                for (int nt = 0; nt < 8; nt++)
#pragma unroll
                    for (int jj = 0; jj < 2; jj++) {
                        float val = fmaxf(fmaf(acc[mt][nt][hf * 2 + jj], 0.015625f, bias_c), 0.0f);
                        const int pl = pw + nt * 8 + tig * 2 + jj;
                        u64 k = ((u64)__float_as_uint(val) << 32) |
                                (u64)(0xFFFFFFFFu - (u32)(pbase + pl));
                        if (k > key) key = k;
                        const int gi = gid_s[pl];
                        g0 = fmaxf(g0, gi == 0 ? val : 0.f);
                        g1 = fmaxf(g1, gi == 1 ? val : 0.f);
                        g2 = fmaxf(g2, gi == 2 ? val : 0.f);
                        g3 = fmaxf(g3, gi == 3 ? val : 0.f);
                    }
                pk[mt][hf] = key;
                gm[mt][hf][0] = g0; gm[mt][hf][1] = g1;
                gm[mt][hf][2] = g2; gm[mt][hf][3] = g3;
            }
        __syncthreads();                 // sync(b): buffer + gid_s reads done
    }

    // single staging + reduce + atomics after all tiles
    u64* skey = reinterpret_cast<u64*>(hbuf0);           // 128*8 u64 = 8 KB
    float* sg = reinterpret_cast<float*>(skey + 1024);   // 128*8*4 f32 = 16 KB
    const int slot = nw * 4 + tig;
#pragma unroll
    for (int mt = 0; mt < 2; mt++)
#pragma unroll
        for (int hf = 0; hf < 2; hf++) {
            const int c = cw + mt * 16 + gid4 + hf * 8;
            skey[c * 8 + slot] = pk[mt][hf];
#pragma unroll
            for (int g = 0; g < 4; g++) sg[(c * 8 + slot) * 4 + g] = gm[mt][hf][g];
        }
    __syncthreads();

    if (tid < 128) {
        const int c = tid;
        u64 m = skey[c * 8];
        float mg[4] = { sg[c * 32 + 0], sg[c * 32 + 1], sg[c * 32 + 2], sg[c * 32 + 3] };
#pragma unroll
        for (int q = 1; q < 8; q++) {
            u64 e = skey[c * 8 + q];
            if (e > m) m = e;
#pragma unroll
            for (int g = 0; g < 4; g++) mg[g] = fmaxf(mg[g], sg[(c * 8 + q) * 4 + g]);
        }
        atomicMax(&g_pmax[b * 1024 + c0 + c], m);
#pragma unroll
        for (int g = 0; g < 4; g++)
            atomicMax(&g_gmax[g * 1024 + c0 + c], __float_as_uint(mg[g]));
    }
}

// ---------------- init + tail MLPs (unchanged) ----------------
__global__ void kInit() {
    int t = blockIdx.x * blockDim.x + threadIdx.x;
    if (t < BATCH * 1024) g_pmax[t] = 0ull;
    if (t < 4 * 1024) g_gmax[t] = 0u;
}

__global__ void kC1(const float* __restrict__ wg0, const float* __restrict__ bg0,
                    const float* __restrict__ wgr0, const float* __restrict__ bgr0,
                    float* __restrict__ out) {
    const int gtid = blockIdx.x * blockDim.x + threadIdx.x;
    if (gtid < BATCH * 1024) {
        unsigned long long pv = g_pmax[gtid];
        out[4096 + gtid] = (float)(0xFFFFFFFFu - (unsigned int)(pv & 0xFFFFFFFFull));
    }
    const int wid = gtid >> 5;
    const int lane = gtid & 31;
    const int row = wid >> 9;
    const int j = wid & 511;
    if (row > 16) return;
    float s = 0.0f;
    if (row < 16) {
        const float* wr = wg0 + (size_t)j * 1024;
        const unsigned long long* pbuf = g_pmax + row * 1024;
        for (int k = lane; k < 1024; k += 32)
            s = fmaf(wr[k], __uint_as_float((unsigned int)(pbuf[k] >> 32)), s);
    } else {
        const float* wr = wgr0 + (size_t)j * 4096;
        for (int k = lane; k < 4096; k += 32)
            s = fmaf(wr[k], __uint_as_float(g_gmax[k]), s);
    }
#pragma unroll
    for (int o = 16; o; o >>= 1) s += __shfl_xor_sync(0xFFFFFFFFu, s, o);
    if (lane == 0) {
        float bb = (row < 16) ? bg0[j] : bgr0[j];
        g_u1[row * 512 + j] = fmaxf(s + bb, 0.0f);
    }
}

__global__ void kC2(const float* __restrict__ wg1, const float* __restrict__ bg1,
                    const float* __restrict__ wgr1, const float* __restrict__ bgr1,
                    float* __restrict__ out) {
    const int gtid = blockIdx.x * blockDim.x + threadIdx.x;
    const int wid = gtid >> 5;
    const int lane = gtid & 31;
    const int row = wid >> 7;
    const int j = wid & 127;
    if (row > 16) return;
    const float* wr = ((row < 16) ? wg1 : wgr1) + (size_t)j * 512;
    const float* in = g_u1 + row * 512;
    float s = 0.0f;
    for (int k = lane; k < 512; k += 32) s = fmaf(wr[k], in[k], s);
#pragma unroll
    for (int o = 16; o; o >>= 1) s += __shfl_xor_sync(0xFFFFFFFFu, s, o);
    s = __shfl_sync(0xFFFFFFFFu, s, 0);
    float bb = (row < 16) ? bg1[j] : bgr1[j];
    float val = fmaxf(s + bb, 0.0f);
    if (row < 16) {
        if (lane == 0) out[row * 256 + 128 + j] = val;
    } else {
        if (lane < 16) out[lane * 256 + j] = val;
    }
}

// ---------------- launch ----------------
extern "C" void kernel_launch(void* const* d_in, const int* in_sizes, int n_in,
                              void* d_out, int out_size) {
    const float* points = (const float*)d_in[0];
    const float* wl0 = (const float*)d_in[1];  const float* bl0 = (const float*)d_in[2];
    const float* wl1 = (const float*)d_in[3];  const float* bl1 = (const float*)d_in[4];
    const float* wl2 = (const float*)d_in[5];  const float* bl2 = (const float*)d_in[6];
    const float* wl3 = (const float*)d_in[7];  const float* bl3 = (const float*)d_in[8];
    const float* wl4 = (const float*)d_in[9];  const float* bl4 = (const float*)d_in[10];
    const float* wg0 = (const float*)d_in[11]; const float* bg0 = (const float*)d_in[12];
    const float* wg1 = (const float*)d_in[13]; const float* bg1 = (const float*)d_in[14];
    const float* wgr0 = (const float*)d_in[15]; const float* bgr0 = (const float*)d_in[16];
    const float* wgr1 = (const float*)d_in[17]; const float* bgr1 = (const float*)d_in[18];
    float* out = (float*)d_out;

    cudaFuncSetAttribute(kA, cudaFuncAttributeMaxDynamicSharedMemorySize,
                         KA_SMEM_FLOATS * (int)sizeof(float));
    cudaFuncSetAttribute(kB, cudaFuncAttributeMaxDynamicSharedMemorySize, KB_SMEM_BYTES);

    kInit<<<64, 256>>>();
    kW<<<256, 256>>>(wl4);
    kA<<<(BATCH * NPTS) / 128, 128, KA_SMEM_FLOATS * sizeof(float)>>>(
        points, wl0, bl0, wl1, bl1, wl2, bl2, wl3, bl3);
    kB<<<1024, 256, KB_SMEM_BYTES>>>(bl4);
    kC1<<<1088, 256>>>(wg0, bg0, wgr0, bgr0, out);
    kC2<<<272, 256>>>(wg1, bg1, wgr1, bgr1, out);
}

// round 13
// speedup vs baseline: 1.5276x; 1.2314x over previous
#include <cuda_runtime.h>
#include <cuda_fp16.h>
#include <cstdint>

#define NPTS 16384
#define BATCH 16
#define INC 7
typedef unsigned long long u64;
typedef unsigned int u32;

// ---------------- scratch ----------------
__device__ u32                g_hhi[(size_t)BATCH * 64 * NPTS]; // (b, kp, i)
__device__ u32                g_hlo[(size_t)BATCH * 64 * NPTS];
__device__ u32                g_wphi[1024 * 64];                // W4 (c, kp), x64
__device__ u32                g_wplo[1024 * 64];
__device__ u32                g_w1hi[64 * 32],  g_w1lo[64 * 32];   // W1 x64
__device__ u32                g_w2hi[64 * 32],  g_w2lo[64 * 32];   // W2 x64
__device__ u32                g_w3hi[128 * 32], g_w3lo[128 * 32];  // W3 x64
__device__ unsigned char      g_gid[BATCH * NPTS];
__device__ unsigned long long g_pmax[BATCH * 1024];
__device__ unsigned int       g_gmax[4 * 1024];
__device__ float              g_u1[17 * 512];

__device__ __forceinline__ void split_limbs(float v, unsigned short& hi, unsigned short& lo) {
    __half h = __float2half_rn(v);
    float r = v - __half2float(h);
    __half l = __float2half_rn(r);
    hi = __half_as_ushort(h);
    lo = __half_as_ushort(l);
}
__device__ __forceinline__ u32 pack_pair(float a, float b) {
    unsigned short h0, l0, h1, l1;
    split_limbs(a, h0, l0); split_limbs(b, h1, l1);
    (void)l0; (void)l1;
    return (u32)h0 | ((u32)h1 << 16);
}
__device__ __forceinline__ void split_pair(float a, float b, u32& hi, u32& lo) {
    unsigned short h0, l0, h1, l1;
    split_limbs(a, h0, l0); split_limbs(b, h1, l1);
    hi = (u32)h0 | ((u32)h1 << 16);
    lo = (u32)l0 | ((u32)l1 << 16);
}
__device__ __forceinline__ void mma16(float* d, const u32* a, const u32* b) {
    asm volatile("mma.sync.aligned.m16n8k16.row.col.f32.f16.f16.f32 "
                 "{%0,%1,%2,%3}, {%4,%5,%6,%7}, {%8,%9}, {%0,%1,%2,%3};"
                 : "+f"(d[0]), "+f"(d[1]), "+f"(d[2]), "+f"(d[3])
                 : "r"(a[0]), "r"(a[1]), "r"(a[2]), "r"(a[3]), "r"(b[0]), "r"(b[1]));
}
__device__ __forceinline__ u32 smem_u32(const void* p) {
    u32 a; asm("{ .reg .u64 t; cvta.to.shared.u64 t, %1; cvt.u32.u64 %0, t; }" : "=r"(a) : "l"(p)); return a;
}
#define CP_ASYNC16(dst, src) asm volatile("cp.async.cg.shared.global [%0], [%1], 16;" :: "r"(dst), "l"(src) : "memory")
#define CP_COMMIT()  asm volatile("cp.async.commit_group;" ::: "memory")
#define CP_WAIT0()   asm volatile("cp.async.wait_group 0;" ::: "memory")
#define CP_WAIT1()   asm volatile("cp.async.wait_group 1;" ::: "memory")

// ================= kernel Wall: split all weights into x64 fp16 limb planes =================
__global__ void kWall(const float* __restrict__ wl1, const float* __restrict__ wl2,
                      const float* __restrict__ wl3, const float* __restrict__ wl4) {
    int T = blockIdx.x * blockDim.x + threadIdx.x;
    const float* src; u32 *dhi, *dlo; int c, kp, K;
    if (T < 2048)       { src = wl1; dhi = g_w1hi; dlo = g_w1lo; int t = T;          c = t >> 5; kp = t & 31; K = 64;  dhi += t; dlo += t; }
    else if (T < 4096)  { src = wl2; dhi = g_w2hi; dlo = g_w2lo; int t = T - 2048;   c = t >> 5; kp = t & 31; K = 64;  dhi += t; dlo += t; }
    else if (T < 8192)  { src = wl3; dhi = g_w3hi; dlo = g_w3lo; int t = T - 4096;   c = t >> 5; kp = t & 31; K = 64;  dhi += t; dlo += t; }
    else if (T < 73728) { src = wl4; dhi = g_wphi; dlo = g_wplo; int t = T - 8192;   c = t >> 6; kp = t & 63; K = 128; dhi += t; dlo += t; }
    else return;
    u32 hi, lo;
    split_pair(src[c * K + 2 * kp] * 64.0f, src[c * K + 2 * kp + 1] * 64.0f, hi, lo);
    *dhi = hi; *dlo = lo;
}

// ================= kernel A: L0 scalar + L1/L2/L3 as 3-pass split-fp16 MMA =================
// smem u32 offsets: wbufA 0 (9216) | wbufB 9216 (4608) | actA 13824 (8704) | actB 22528 (8704) | stage 31232 (16640 f32)
#define OFF_WBA 0
#define OFF_WBB 9216
#define OFF_ACTA 13824
#define OFF_ACTB 22528
#define OFF_STAGE 31232
#define KA_SMEM_U32 47872
#define ACT_PL 4352          // act plane size: 32*136
#define AST 136              // act row stride
#define WST 36               // w row stride

__device__ __forceinline__ void cpw(u32 dst, const u32* hi, const u32* lo, int C, int tid) {
    const int chunks = C * 8;                 // uint4 per plane
    for (int j = tid; j < 2 * chunks; j += 256) {
        int plane = (j >= chunks);
        int r = (j - plane * chunks) >> 3;
        int q = (j & 7) * 4;
        const u32* src = (plane ? lo : hi) + r * 32 + q;
        CP_ASYNC16(dst + (u32)(plane * C * WST + r * WST + q) * 4, src);
    }
}

// mainloop + stage write for one layer. MT=1: 16ch/warp slab, MT=2: 32ch/warp.
template <int MT>
__device__ __forceinline__ void layer_mma(const u32* __restrict__ wb, int wplane,
                                          const u32* __restrict__ act,
                                          float* __restrict__ stage,
                                          const float* __restrict__ bias, int tid) {
    const int lane = tid & 31, wrp = tid >> 5;
    const int mw = wrp >> 1, nw = wrp & 1;
    const int gid4 = lane >> 2, tig = lane & 3;
    const int cw = mw * (MT * 16), pw = nw * 64;

    float acc[MT][8][4];
#pragma unroll
    for (int mt = 0; mt < MT; mt++)
#pragma unroll
        for (int nt = 0; nt < 8; nt++)
#pragma unroll
            for (int j = 0; j < 4; j++) acc[mt][nt][j] = 0.0f;

#pragma unroll
    for (int kk = 0; kk < 4; kk++) {
        const int kpb = kk * 8;
        u32 ahi[MT][4], alo[MT][4];
#pragma unroll
        for (int mt = 0; mt < MT; mt++) {
            const int r0 = cw + mt * 16 + gid4;
#pragma unroll
            for (int q = 0; q < 4; q++) {
                const int rr = r0 + (q & 1) * 8;
                const int kq = kpb + tig + (q >> 1) * 4;
                ahi[mt][q] = wb[rr * WST + kq];
                alo[mt][q] = wb[wplane + rr * WST + kq];
            }
        }
        u32 bhi[8][2], blo[8][2];
#pragma unroll
        for (int nt = 0; nt < 8; nt++) {
            const int pp = pw + nt * 8 + gid4;
#pragma unroll
            for (int q = 0; q < 2; q++) {
                const int kr = kpb + tig + q * 4;
                bhi[nt][q] = act[kr * AST + pp];
                blo[nt][q] = act[ACT_PL + kr * AST + pp];
            }
        }
#pragma unroll
        for (int mt = 0; mt < MT; mt++)
#pragma unroll
            for (int nt = 0; nt < 8; nt++) {
                mma16(acc[mt][nt], ahi[mt], bhi[nt]);
                mma16(acc[mt][nt], ahi[mt], blo[nt]);
                mma16(acc[mt][nt], alo[mt], bhi[nt]);
            }
    }
    // bias + relu + stage write (scale 1/64 for x64 weights)
#pragma unroll
    for (int mt = 0; mt < MT; mt++)
#pragma unroll
        for (int hf = 0; hf < 2; hf++) {
            const int c = cw + mt * 16 + gid4 + hf * 8;
            const float bias_c = __ldg(&bias[c]);
#pragma unroll
            for (int nt = 0; nt < 8; nt++)
#pragma unroll
                for (int jj = 0; jj < 2; jj++) {
                    float val = fmaxf(fmaf(acc[mt][nt][hf * 2 + jj], 0.015625f, bias_c), 0.0f);
                    stage[c * 130 + pw + nt * 8 + tig * 2 + jj] = val;
                }
        }
}

__global__ __launch_bounds__(256, 1)
void kA(const float* __restrict__ points,
        const float* __restrict__ wl0, const float* __restrict__ bl0,
        const float* __restrict__ bl1, const float* __restrict__ bl2,
        const float* __restrict__ bl3) {
    extern __shared__ u32 smu[];
    u32* wbufA = smu + OFF_WBA;
    u32* wbufB = smu + OFF_WBB;
    u32* actA  = smu + OFF_ACTA;
    u32* actB  = smu + OFF_ACTB;
    float* stage = reinterpret_cast<float*>(smu + OFF_STAGE);
    const u32 sbase = smem_u32(smu);
    const int tid = threadIdx.x;
    const int bid = blockIdx.x;
    const int b = bid >> 7;
    const int pbase = (bid & 127) * 128;

    // prefetch W1 into wbufA
    cpw(sbase + OFF_WBA * 4, g_w1hi, g_w1lo, 64, tid);
    CP_COMMIT();

    // stage W0|b0 in fp32 at stage[0..512)
    for (int i = tid; i < 448; i += 256) stage[i] = wl0[i];
    for (int i = tid; i < 64; i += 256) stage[448 + i] = bl0[i];
    __syncthreads();

    // L0: 7 -> 64 scalar, write limb act tile
    {
        const int pt = tid & 127, seg = tid >> 7;
        const float* ptp = points + (size_t)b * INC * NPTS + pbase + pt;
        float x[INC];
#pragma unroll
        for (int c = 0; c < INC; c++) x[c] = ptp[(size_t)c * NPTS];
        if (seg == 0) {
            int g = 0; float bv = x[3];
            if (x[4] > bv) { bv = x[4]; g = 1; }
            if (x[5] > bv) { bv = x[5]; g = 2; }
            if (x[6] > bv) { bv = x[6]; g = 3; }
            g_gid[b * NPTS + pbase + pt] = (unsigned char)g;
        }
#pragma unroll 4
        for (int kp = seg * 16; kp < seg * 16 + 16; kp++) {
            const int c = 2 * kp;
            const float* w0 = stage + c * 7;
            const float* w1 = w0 + 7;
            float s0 = stage[448 + c], s1 = stage[448 + c + 1];
#pragma unroll
            for (int k = 0; k < INC; k++) { s0 = fmaf(w0[k], x[k], s0); s1 = fmaf(w1[k], x[k], s1); }
            u32 hi, lo;
            split_pair(fmaxf(s0, 0.0f), fmaxf(s1, 0.0f), hi, lo);
            actA[kp * AST + pt] = hi;
            actA[ACT_PL + kp * AST + pt] = lo;
        }
    }
    CP_WAIT0();
    __syncthreads();                      // W1 + actA(L0) + stage(W0 reads done) visible

    // prefetch W2 (overlaps L1)
    cpw(sbase + OFF_WBB * 4, g_w2hi, g_w2lo, 64, tid);
    CP_COMMIT();

    // L1: wbufA x actA -> stage
    layer_mma<1>(wbufA, 64 * WST, actA, stage, bl1, tid);
    __syncthreads();
    // split stage -> actB
    {
        const int pt = tid & 127, seg = tid >> 7;
#pragma unroll 4
        for (int kp = seg * 16; kp < seg * 16 + 16; kp++) {
            u32 hi, lo;
            split_pair(stage[(2 * kp) * 130 + pt], stage[(2 * kp + 1) * 130 + pt], hi, lo);
            actB[kp * AST + pt] = hi;
            actB[ACT_PL + kp * AST + pt] = lo;
        }
    }
    cpw(sbase + OFF_WBA * 4, g_w3hi, g_w3lo, 128, tid);   // W3 into wbufA (free: L1 done)
    CP_COMMIT();
    CP_WAIT1();                            // W2 ready (W3 pending)
    __syncthreads();                       // actB visible

    // L2: wbufB x actB -> stage
    layer_mma<1>(wbufB, 64 * WST, actB, stage, bl2, tid);
    __syncthreads();
    // split stage -> actA
    {
        const int pt = tid & 127, seg = tid >> 7;
#pragma unroll 4
        for (int kp = seg * 16; kp < seg * 16 + 16; kp++) {
            u32 hi, lo;
            split_pair(stage[(2 * kp) * 130 + pt], stage[(2 * kp + 1) * 130 + pt], hi, lo);
            actA[kp * AST + pt] = hi;
            actA[ACT_PL + kp * AST + pt] = lo;
        }
    }
    CP_WAIT0();                            // W3 ready
    __syncthreads();                       // actA visible

    // L3: wbufA(128ch) x actA -> stage(128x130)
    layer_mma<2>(wbufA, 128 * WST, actA, stage, bl3, tid);
    __syncthreads();
    // split stage -> global limb planes (b, kp, i)
    {
        const int pt = tid & 127, seg = tid >> 7;
#pragma unroll 4
        for (int kp = seg * 32; kp < seg * 32 + 32; kp++) {
            u32 hi, lo;
            split_pair(stage[(2 * kp) * 130 + pt], stage[(2 * kp + 1) * 130 + pt], hi, lo);
            g_hhi[((size_t)b * 64 + kp) * NPTS + pbase + pt] = hi;
            g_hlo[((size_t)b * 64 + kp) * NPTS + pbase + pt] = lo;
        }
    }
}

// ================= kernel B: R12 proven (register-running reductions) =================
#define WS2 68
#define HS2 136
#define KB_W_U (2 * 128 * WS2)
#define KB_H_U (2 * 64 * HS2)
#define KB_SMEM_BYTES ((KB_W_U + 2 * KB_H_U) * 4)

__global__ __launch_bounds__(256, 1)
void kB(const float* __restrict__ bl4) {
    extern __shared__ float smf[];
    u32* swp = reinterpret_cast<u32*>(smf);
    u32* hbuf0 = swp + KB_W_U;
    u32* hbuf1 = hbuf0 + KB_H_U;
    __shared__ unsigned char gid_s[128];

    const int tid = threadIdx.x;
    const int bid = blockIdx.x;
    const int b  = bid >> 6;
    const int pg = (bid >> 3) & 7;
    const int cc = bid & 7;
    const int c0 = cc * 128;

#pragma unroll
    for (int j = 0; j < 8; j++) {
        int idx = j * 256 + tid;
        int r = idx >> 4, q = (idx & 15) * 4;
        uint4 vh = *reinterpret_cast<const uint4*>(g_wphi + (size_t)(c0 + r) * 64 + q);
        uint4 vl = *reinterpret_cast<const uint4*>(g_wplo + (size_t)(c0 + r) * 64 + q);
        *reinterpret_cast<uint4*>(&swp[r * WS2 + q]) = vh;
        *reinterpret_cast<uint4*>(&swp[128 * WS2 + r * WS2 + q]) = vl;
    }

    const u32 hadd[2] = { smem_u32(hbuf0), smem_u32(hbuf1) };
    {
        const int pbase = pg * 2048;
#pragma unroll
        for (int j = 0; j < 16; j++) {
            int idx = j * 256 + tid;
            int row = idx >> 5, q = (idx & 31) * 4;
            const u32* src = (row < 64)
                ? g_hhi + ((size_t)b * 64 + row) * NPTS + pbase + q
                : g_hlo + ((size_t)b * 64 + (row - 64)) * NPTS + pbase + q;
            CP_ASYNC16(hadd[0] + (u32)(row * HS2 + q) * 4, src);
        }
        CP_COMMIT();
    }

    const int lane = tid & 31, wrp = tid >> 5;
    const int mw = wrp >> 1;
    const int nw = wrp & 1;
    const int gid4 = lane >> 2, tig = lane & 3;
    const int cw = mw * 32, pw = nw * 64;

    float biasr[2][2];
    u64 pk[2][2];
    float gm[2][2][4];
#pragma unroll
    for (int mt = 0; mt < 2; mt++)
#pragma unroll
        for (int hf = 0; hf < 2; hf++) {
            biasr[mt][hf] = __ldg(&bl4[c0 + cw + mt * 16 + gid4 + hf * 8]);
            pk[mt][hf] = 0ull;
#pragma unroll
            for (int g = 0; g < 4; g++) gm[mt][hf][g] = 0.0f;
        }

#pragma unroll 1
    for (int t = 0; t < 16; t++) {
        const int pbase = (pg * 16 + t) * 128;
        u32* shp = (t & 1) ? hbuf1 : hbuf0;
        if (t + 1 < 16) {
            const int pn = (pg * 16 + t + 1) * 128;
            const u32 dsta = hadd[(t + 1) & 1];
#pragma unroll
            for (int j = 0; j < 16; j++) {
                int idx = j * 256 + tid;
                int row = idx >> 5, q = (idx & 31) * 4;
                const u32* src = (row < 64)
                    ? g_hhi + ((size_t)b * 64 + row) * NPTS + pn + q
                    : g_hlo + ((size_t)b * 64 + (row - 64)) * NPTS + pn + q;
                CP_ASYNC16(dsta + (u32)(row * HS2 + q) * 4, src);
            }
            CP_COMMIT();
            CP_WAIT1();
        } else {
            CP_WAIT0();
        }
        if (tid < 128) gid_s[tid] = g_gid[b * NPTS + pbase + tid];
        __syncthreads();

        float acc[2][8][4];
#pragma unroll
        for (int mt = 0; mt < 2; mt++)
#pragma unroll
            for (int nt = 0; nt < 8; nt++)
#pragma unroll
                for (int j = 0; j < 4; j++) acc[mt][nt][j] = 0.0f;

        const u32* swhi = swp;
        const u32* swlo = swp + 128 * WS2;
        const u32* shhi = shp;
        const u32* shlo = shp + 64 * HS2;

#pragma unroll 1
        for (int kk = 0; kk < 8; kk++) {
            const int kpb = kk * 8;
            u32 ahi[2][4], alo[2][4];
#pragma unroll
            for (int mt = 0; mt < 2; mt++) {
                const int r0 = cw + mt * 16 + gid4;
#pragma unroll
                for (int q = 0; q < 4; q++) {
                    const int rr = r0 + (q & 1) * 8;
                    const int kq = kpb + tig + (q >> 1) * 4;
                    ahi[mt][q] = swhi[rr * WS2 + kq];
                    alo[mt][q] = swlo[rr * WS2 + kq];
                }
            }
            u32 bhi[8][2], blo[8][2];
#pragma unroll
            for (int nt = 0; nt < 8; nt++) {
                const int pp = pw + nt * 8 + gid4;
#pragma unroll
                for (int q = 0; q < 2; q++) {
                    const int kr = kpb + tig + q * 4;
                    bhi[nt][q] = shhi[kr * HS2 + pp];
                    blo[nt][q] = shlo[kr * HS2 + pp];
                }
            }
#pragma unroll
            for (int mt = 0; mt < 2; mt++)
#pragma unroll
                for (int nt = 0; nt < 8; nt++) {
                    mma16(acc[mt][nt], ahi[mt], bhi[nt]);
                    mma16(acc[mt][nt], ahi[mt], blo[nt]);
                    mma16(acc[mt][nt], alo[mt], bhi[nt]);
                }
        }

#pragma unroll
        for (int mt = 0; mt < 2; mt++)
#pragma unroll
            for (int hf = 0; hf < 2; hf++) {
                const float bias_c = biasr[mt][hf];
                u64 key = pk[mt][hf];
                float g0 = gm[mt][hf][0], g1 = gm[mt][hf][1];
                float g2 = gm[mt][hf][2], g3 = gm[mt][hf][3];
#pragma unroll
                for (int nt = 0; nt < 8; nt++)
#pragma unroll
                    for (int jj = 0; jj < 2; jj++) {
                        float val = fmaxf(fmaf(acc[mt][nt][hf * 2 + jj], 0.015625f, bias_c), 0.0f);
                        const int pl = pw + nt * 8 + tig * 2 + jj;
                        u64 k = ((u64)__float_as_uint(val) << 32) |
                                (u64)(0xFFFFFFFFu - (u32)(pbase + pl));
                        if (k > key) key = k;
                        const int gi = gid_s[pl];
                        g0 = fmaxf(g0, gi == 0 ? val : 0.f);
                        g1 = fmaxf(g1, gi == 1 ? val : 0.f);
                        g2 = fmaxf(g2, gi == 2 ? val : 0.f);
                        g3 = fmaxf(g3, gi == 3 ? val : 0.f);
                    }
                pk[mt][hf] = key;
                gm[mt][hf][0] = g0; gm[mt][hf][1] = g1;
                gm[mt][hf][2] = g2; gm[mt][hf][3] = g3;
            }
        __syncthreads();
    }

    u64* skey = reinterpret_cast<u64*>(hbuf0);
    float* sg = reinterpret_cast<float*>(skey + 1024);
    const int slot = nw * 4 + tig;
#pragma unroll
    for (int mt = 0; mt < 2; mt++)
#pragma unroll
        for (int hf = 0; hf < 2; hf++) {
            const int c = cw + mt * 16 + gid4 + hf * 8;
            skey[c * 8 + slot] = pk[mt][hf];
#pragma unroll
            for (int g = 0; g < 4; g++) sg[(c * 8 + slot) * 4 + g] = gm[mt][hf][g];
        }
    __syncthreads();

    if (tid < 128) {
        const int c = tid;
        u64 m = skey[c * 8];
        float mg[4] = { sg[c * 32 + 0], sg[c * 32 + 1], sg[c * 32 + 2], sg[c * 32 + 3] };
#pragma unroll
        for (int q = 1; q < 8; q++) {
            u64 e = skey[c * 8 + q];
            if (e > m) m = e;
#pragma unroll
            for (int g = 0; g < 4; g++) mg[g] = fmaxf(mg[g], sg[(c * 8 + q) * 4 + g]);
        }
        atomicMax(&g_pmax[b * 1024 + c0 + c], m);
#pragma unroll
        for (int g = 0; g < 4; g++)
            atomicMax(&g_gmax[g * 1024 + c0 + c], __float_as_uint(mg[g]));
    }
}

// ---------------- init + tail MLPs (unchanged) ----------------
__global__ void kInit() {
    int t = blockIdx.x * blockDim.x + threadIdx.x;
    if (t < BATCH * 1024) g_pmax[t] = 0ull;
    if (t < 4 * 1024) g_gmax[t] = 0u;
}

__global__ void kC1(const float* __restrict__ wg0, const float* __restrict__ bg0,
                    const float* __restrict__ wgr0, const float* __restrict__ bgr0,
                    float* __restrict__ out) {
    const int gtid = blockIdx.x * blockDim.x + threadIdx.x;
    if (gtid < BATCH * 1024) {
        unsigned long long pv = g_pmax[gtid];
        out[4096 + gtid] = (float)(0xFFFFFFFFu - (unsigned int)(pv & 0xFFFFFFFFull));
    }
    const int wid = gtid >> 5;
    const int lane = gtid & 31;
    const int row = wid >> 9;
    const int j = wid & 511;
    if (row > 16) return;
    float s = 0.0f;
    if (row < 16) {
        const float* wr = wg0 + (size_t)j * 1024;
        const unsigned long long* pbuf = g_pmax + row * 1024;
        for (int k = lane; k < 1024; k += 32)
            s = fmaf(wr[k], __uint_as_float((unsigned int)(pbuf[k] >> 32)), s);
    } else {
        const float* wr = wgr0 + (size_t)j * 4096;
        for (int k = lane; k < 4096; k += 32)
            s = fmaf(wr[k], __uint_as_float(g_gmax[k]), s);
    }
#pragma unroll
    for (int o = 16; o; o >>= 1) s += __shfl_xor_sync(0xFFFFFFFFu, s, o);
    if (lane == 0) {
        float bb = (row < 16) ? bg0[j] : bgr0[j];
        g_u1[row * 512 + j] = fmaxf(s + bb, 0.0f);
    }
}

__global__ void kC2(const float* __restrict__ wg1, const float* __restrict__ bg1,
                    const float* __restrict__ wgr1, const float* __restrict__ bgr1,
                    float* __restrict__ out) {
    const int gtid = blockIdx.x * blockDim.x + threadIdx.x;
    const int wid = gtid >> 5;
    const int lane = gtid & 31;
    const int row = wid >> 7;
    const int j = wid & 127;
    if (row > 16) return;
    const float* wr = ((row < 16) ? wg1 : wgr1) + (size_t)j * 512;
    const float* in = g_u1 + row * 512;
    float s = 0.0f;
    for (int k = lane; k < 512; k += 32) s = fmaf(wr[k], in[k], s);
#pragma unroll
    for (int o = 16; o; o >>= 1) s += __shfl_xor_sync(0xFFFFFFFFu, s, o);
    s = __shfl_sync(0xFFFFFFFFu, s, 0);
    float bb = (row < 16) ? bg1[j] : bgr1[j];
    float val = fmaxf(s + bb, 0.0f);
    if (row < 16) {
        if (lane == 0) out[row * 256 + 128 + j] = val;
    } else {
        if (lane < 16) out[lane * 256 + j] = val;
    }
}

// ---------------- launch ----------------
extern "C" void kernel_launch(void* const* d_in, const int* in_sizes, int n_in,
                              void* d_out, int out_size) {
    const float* points = (const float*)d_in[0];
    const float* wl0 = (const float*)d_in[1];  const float* bl0 = (const float*)d_in[2];
    const float* wl1 = (const float*)d_in[3];  const float* bl1 = (const float*)d_in[4];
    const float* wl2 = (const float*)d_in[5];  const float* bl2 = (const float*)d_in[6];
    const float* wl3 = (const float*)d_in[7];  const float* bl3 = (const float*)d_in[8];
    const float* wl4 = (const float*)d_in[9];  const float* bl4 = (const float*)d_in[10];
    const float* wg0 = (const float*)d_in[11]; const float* bg0 = (const float*)d_in[12];
    const float* wg1 = (const float*)d_in[13]; const float* bg1 = (const float*)d_in[14];
    const float* wgr0 = (const float*)d_in[15]; const float* bgr0 = (const float*)d_in[16];
    const float* wgr1 = (const float*)d_in[17]; const float* bgr1 = (const float*)d_in[18];
    float* out = (float*)d_out;

    cudaFuncSetAttribute(kA, cudaFuncAttributeMaxDynamicSharedMemorySize,
                         KA_SMEM_U32 * (int)sizeof(u32));
    cudaFuncSetAttribute(kB, cudaFuncAttributeMaxDynamicSharedMemorySize, KB_SMEM_BYTES);

    kInit<<<64, 256>>>();
    kWall<<<288, 256>>>(wl1, wl2, wl3, wl4);
    kA<<<BATCH * NPTS / 128, 256, KA_SMEM_U32 * sizeof(u32)>>>(
        points, wl0, bl0, bl1, bl2, bl3);
    kB<<<1024, 256, KB_SMEM_BYTES>>>(bl4);
    kC1<<<1088, 256>>>(wg0, bg0, wgr0, bgr0, out);
    kC2<<<272, 256>>>(wg1, bg1, wgr1, bgr1, out);
}